// round 9
// baseline (speedup 1.0000x reference)
#include <cuda_runtime.h>
#include <math.h>

#define B_   2
#define L_   2048
#define D_   1024
#define DH_  1024
#define NH_  8
#define HD_  128

#define BM 128
#define BN 128
#define BKQ 16
#define LDT 136
#define NT 256

// ---------------- scratch (device globals; no allocation) ----------------
__device__ float g_q[(size_t)B_*NH_*L_*HD_];      // [b][n][l][h]
__device__ float g_k[(size_t)B_*NH_*L_*HD_];      // [b][n][l][h]
__device__ float g_v[(size_t)B_*L_*D_];           // [b][l][d]
__device__ float g_projlr[(size_t)B_*L_*NH_];
__device__ float g_projwd[(size_t)B_*L_*NH_];
__device__ float g_lr[(size_t)B_*NH_*L_];
__device__ float g_lwd[(size_t)B_*NH_*L_];
__device__ float g_wdcross[(size_t)B_*NH_*L_];
__device__ float g_winl[(size_t)B_*NH_*L_];
__device__ float g_wdclast[B_*NH_];
__device__ float g_A[(size_t)B_*NH_*L_*D_];       // lr[l]*(k·Wp^T - v)   [bn][l][d]
__device__ float g_C[(size_t)B_*NH_*L_*L_];       // NEGATED masked kq    [bn][l][m]

// ---------------- tf32 helpers ----------------
__device__ __forceinline__ unsigned f2tf(float x){
    unsigned r; asm("cvt.rna.tf32.f32 %0, %1;" : "=r"(r) : "f"(x)); return r;
}
__device__ __forceinline__ float tfhi(float x){ return __uint_as_float(f2tf(x)); }

__device__ __forceinline__ void mma8(float (&d)[4], const unsigned (&a)[4], const unsigned (&b)[2]){
    asm volatile("mma.sync.aligned.m16n8k8.row.col.f32.tf32.tf32.f32 "
        "{%0,%1,%2,%3}, {%4,%5,%6,%7}, {%8,%9}, {%0,%1,%2,%3};\n"
        : "+f"(d[0]),"+f"(d[1]),"+f"(d[2]),"+f"(d[3])
        : "r"(a[0]),"r"(a[1]),"r"(a[2]),"r"(a[3]),"r"(b[0]),"r"(b[1]));
}

// ---------------- fragment loads (smem stored [k][m/n], ld=LDT) ----------------
__device__ __forceinline__ void ldfragA(const float* As, int ksb, int Wm, int lane, unsigned (&a)[4][4]){
    int g = lane>>2, t = lane&3;
    const float* p = As + (ksb + t)*LDT + Wm + g;
#pragma unroll
    for (int mt=0; mt<4; mt++){
        a[mt][0] = __float_as_uint(p[mt*16]);
        a[mt][1] = __float_as_uint(p[mt*16+8]);
        a[mt][2] = __float_as_uint(p[4*LDT+mt*16]);
        a[mt][3] = __float_as_uint(p[4*LDT+mt*16+8]);
    }
}
__device__ __forceinline__ void ldfragB(const float* Bs, int ksb, int Wn, int lane, unsigned (&bf)[4][2]){
    int g = lane>>2, t = lane&3;
    const float* p = Bs + (ksb + t)*LDT + Wn + g;
#pragma unroll
    for (int nt=0; nt<4; nt++){
        bf[nt][0] = __float_as_uint(p[nt*8]);
        bf[nt][1] = __float_as_uint(p[4*LDT+nt*8]);
    }
}
__device__ __forceinline__ void mma_tiles(const unsigned (&a)[4][4], const unsigned (&bf)[4][2], float (&acc)[4][4][4]){
#pragma unroll
    for (int mt=0;mt<4;mt++)
#pragma unroll
        for (int nt=0;nt<4;nt++)
            mma8(acc[mt][nt], a[mt], bf[nt]);
}
__device__ __forceinline__ void compute_1x(const float* As, const float* Bs,
                                           float (&acc)[4][4][4], int lane, int Wm, int Wn){
#pragma unroll
    for (int ks=0; ks<2; ks++){
        unsigned a[4][4], bf[4][2];
        ldfragA(As, ks*8, Wm, lane, a);
        ldfragB(Bs, ks*8, Wn, lane, bf);
        mma_tiles(a, bf, acc);
    }
}
__device__ __forceinline__ void compute_3x(const float* Ah, const float* Al,
                                           const float* Bh, const float* Bl,
                                           float (&acc)[4][4][4], int lane, int Wm, int Wn){
#pragma unroll
    for (int ks=0; ks<2; ks++){
        unsigned ah[4][4], al[4][4], bh[4][2], bl[4][2];
        ldfragA(Ah, ks*8, Wm, lane, ah);
        ldfragB(Bh, ks*8, Wn, lane, bh);
        mma_tiles(ah, bh, acc);
        ldfragA(Al, ks*8, Wm, lane, al);
        mma_tiles(al, bh, acc);
        ldfragB(Bl, ks*8, Wn, lane, bl);
        mma_tiles(ah, bl, acc);
    }
}

// ---------------- tile loaders (split ldg / sts for pipelining) ----------------
// transpose: src row-major [R][K], dst[k][r]
__device__ __forceinline__ void ldg_trans(const float* src, int sld, int r0, int k0, int tid, float4 (&o)[2]){
    const float* p = src + (size_t)(r0 + (tid>>1))*sld + k0 + (tid&1)*4;
    o[0] = *(const float4*)(p);
    o[1] = *(const float4*)(p+8);
}
template<bool SPLIT>
__device__ __forceinline__ void sts_trans(const float4 (&o)[2], float s, float* dhi, float* dlo, int tid){
    int r = tid>>1, kk=(tid&1)*4;
#pragma unroll
    for (int p=0;p<2;p++){
        float vv[4]={o[p].x,o[p].y,o[p].z,o[p].w};
#pragma unroll
        for (int i=0;i<4;i++){
            float x = vv[i]*s;
            float hi = tfhi(x);
            dhi[(kk+8*p+i)*LDT + r] = hi;
            if (SPLIT) dlo[(kk+8*p+i)*LDT + r] = tfhi(x-hi);
        }
    }
}
// direct: src row-major [K][N], dst[k][n]
__device__ __forceinline__ void ldg_dir(const float* src, int sld, int k0, int n0, int tid, float4 (&o)[2]){
    const float* p = src + (size_t)(k0 + (tid>>5))*sld + n0 + (tid&31)*4;
    o[0] = *(const float4*)(p);
    o[1] = *(const float4*)(p + (size_t)8*sld);
}
template<bool SPLIT>
__device__ __forceinline__ void sts_dir(const float4 (&o)[2], float s0, float s1, float* dhi, float* dlo, int tid){
    int k = tid>>5, n=(tid&31)*4;
    float sc[2]={s0,s1};
#pragma unroll
    for (int p=0;p<2;p++){
        float vv[4]={o[p].x,o[p].y,o[p].z,o[p].w};
        float h4[4], lo4[4];
#pragma unroll
        for (int i=0;i<4;i++){
            float x=vv[i]*sc[p];
            h4[i]=tfhi(x);
            lo4[i]= SPLIT? tfhi(x-h4[i]) : 0.f;
        }
        *(float4*)(dhi + (k+8*p)*LDT + n) = make_float4(h4[0],h4[1],h4[2],h4[3]);
        if (SPLIT) *(float4*)(dlo + (k+8*p)*LDT + n) = make_float4(lo4[0],lo4[1],lo4[2],lo4[3]);
    }
}

// ---------------- K1: Q/K/V projections (3xTF32) ----------------
__global__ __launch_bounds__(NT) void k_proj_qkv(
    const float* __restrict__ x,
    const float* __restrict__ wq, const float* __restrict__ bq,
    const float* __restrict__ wk, const float* __restrict__ bk,
    const float* __restrict__ wv, const float* __restrict__ bv)
{
    __shared__ __align__(16) float sAh[BKQ*LDT], sAl[BKQ*LDT], sBh[BKQ*LDT], sBl[BKQ*LDT];
    int t = blockIdx.z % 3, b = blockIdx.z / 3;
    const float* W    = (t==0)?wq:((t==1)?wk:wv);
    const float* bias = (t==0)?bq:((t==1)?bk:bv);
    int m0g = blockIdx.x*BM, n0g = blockIdx.y*BN;
    const float* Xb = x + (size_t)b*L_*D_;
    int tid = threadIdx.x, lane = tid&31, w = tid>>5;
    int Wm = (w>>2)*64, Wn = (w&3)*32;
    float acc[4][4][4] = {};
    float4 pa[2], pb[2];
    const int KT = D_/BKQ;
    ldg_trans(Xb, D_, m0g, 0, tid, pa);
    ldg_dir(W, DH_, 0, n0g, tid, pb);
    for (int it=0; it<KT; ++it){
        sts_trans<true>(pa, 1.f, sAh, sAl, tid);
        sts_dir<true>(pb, 1.f, 1.f, sBh, sBl, tid);
        __syncthreads();
        if (it+1<KT){
            ldg_trans(Xb, D_, m0g, (it+1)*BKQ, tid, pa);
            ldg_dir(W, DH_, (it+1)*BKQ, n0g, tid, pb);
        }
        compute_3x(sAh,sAl,sBh,sBl,acc,lane,Wm,Wn);
        __syncthreads();
    }
    int g=lane>>2, t4=lane&3;
#pragma unroll
    for (int mt=0;mt<4;mt++){
        int mb = m0g + Wm + mt*16 + g;
#pragma unroll
        for (int nt=0;nt<4;nt++){
            int jg = n0g + Wn + nt*8 + 2*t4;
            float b0 = bias[jg], b1 = bias[jg+1];
#pragma unroll
            for (int rr=0; rr<2; rr++){
                int m = mb + rr*8;
                float v0 = acc[mt][nt][rr*2+0]+b0, v1 = acc[mt][nt][rr*2+1]+b1;
                if (t==2){
                    *(float2*)&g_v[((size_t)b*L_+m)*D_ + jg] = make_float2(v0,v1);
                } else {
                    int hd = jg>>7, h = jg&127;
                    float* dst = (t==0)? g_q : g_k;
                    *(float2*)&dst[(((size_t)b*NH_+hd)*L_+m)*HD_ + h] = make_float2(v0,v1);
                }
            }
        }
    }
}

// ---------------- K2: lr/wd tiny projections ----------------
__global__ __launch_bounds__(NT) void k_proj_lrwd(
    const float* __restrict__ x,
    const float* __restrict__ fclw, const float* __restrict__ fclb,
    const float* __restrict__ fcww, const float* __restrict__ fcwb)
{
    int gw = (blockIdx.x * blockDim.x + threadIdx.x) >> 5;
    int lane = threadIdx.x & 31;
    if (gw >= B_ * L_) return;
    const float* xr = x + (size_t)gw * D_;
    float acc[16];
#pragma unroll
    for (int j = 0; j < 16; ++j) acc[j] = 0.f;
    for (int k = lane; k < D_; k += 32) {
        float xv = xr[k];
        const float* r1 = fclw + k * NH_;
        const float* r2 = fcww + k * NH_;
#pragma unroll
        for (int j = 0; j < 8; ++j) {
            acc[j]     += xv * r1[j];
            acc[8 + j] += xv * r2[j];
        }
    }
#pragma unroll
    for (int off = 16; off; off >>= 1)
#pragma unroll
        for (int j = 0; j < 16; ++j)
            acc[j] += __shfl_xor_sync(0xffffffffu, acc[j], off);
    if (lane == 0) {
#pragma unroll
        for (int j = 0; j < 8; ++j) {
            g_projlr[(size_t)gw * NH_ + j] = acc[j] + fclb[j];
            g_projwd[(size_t)gw * NH_ + j] = acc[8 + j] + fcwb[j];
        }
    }
}

// ---------------- K3: nonlinearity + parallel scan ----------------
__global__ __launch_bounds__(NT) void k_scan(
    const float* __restrict__ log_base_lr, const float* __restrict__ log_base_wd)
{
    __shared__ float s_lwd[L_];
    __shared__ float sp[NT];
    int bn = blockIdx.x, b = bn >> 3, n = bn & 7;
    int tid = threadIdx.x;
    float blr = expf(log_base_lr[n]);
    float bwd = expf(log_base_wd[n]);
    for (int l = tid; l < L_; l += NT) {
        float plr = g_projlr[((size_t)b*L_+l)*NH_ + n];
        g_lr[(size_t)bn*L_ + l] = blr / (1.f + expf(-plr));
        float pwd = g_projwd[((size_t)b*L_+l)*NH_ + n];
        float lwd = log1pf(-bwd / (1.f + expf(-pwd)));
        s_lwd[l] = lwd;
        g_lwd[(size_t)bn*L_ + l] = lwd;
    }
    __syncthreads();
    // per-thread 8-chunk sums
    const int CH = L_/NT; // 8
    float loc[CH];
    float part = 0.f;
#pragma unroll
    for (int i=0;i<CH;i++){ loc[i] = s_lwd[tid*CH + i]; part += loc[i]; }
    sp[tid] = part;
    __syncthreads();
    for (int off=1; off<NT; off<<=1){
        float v = (tid>=off)? sp[tid-off] : 0.f;
        __syncthreads();
        sp[tid] += v;
        __syncthreads();
    }
    float pre = sp[tid] - part;  // exclusive prefix of this chunk
    float lwdlast = s_lwd[L_-1];
    float run = pre;
#pragma unroll
    for (int i=0;i<CH;i++){
        int l = tid*CH + i;
        run += loc[i];
        g_wdcross[(size_t)bn*L_ + l] = expf(run);
        int mn = min(l+1, L_-1);
        g_winl[(size_t)bn*L_ + l] = expf(lwdlast * (float)mn);
    }
    if (tid == NT-1) g_wdclast[bn] = expf(sp[NT-1]);
}

// ---------------- K4: A = lr*(k·Wp^T - v)   (3xTF32) ----------------
__global__ __launch_bounds__(NT) void k_A(const float* __restrict__ hidden)
{
    __shared__ __align__(16) float sAh[BKQ*LDT], sAl[BKQ*LDT], sBh[BKQ*LDT], sBl[BKQ*LDT];
    int bn = blockIdx.z, b = bn>>3, n = bn&7;
    int l0g = blockIdx.x*BM, d0g = blockIdx.y*BN;
    const float* kb  = g_k + (size_t)bn*L_*HD_;
    const float* hid = hidden + (size_t)b*D_*DH_ + n*HD_;
    int tid = threadIdx.x, lane = tid&31, w = tid>>5;
    int Wm = (w>>2)*64, Wn = (w&3)*32;
    float acc[4][4][4] = {};
    float4 pa[2], pb[2];
    const int KT = HD_/BKQ;
    ldg_trans(kb, HD_, l0g, 0, tid, pa);
    ldg_trans(hid, DH_, d0g, 0, tid, pb);
    for (int it=0; it<KT; ++it){
        sts_trans<true>(pa, 1.f, sAh, sAl, tid);
        sts_trans<true>(pb, 1.f, sBh, sBl, tid);
        __syncthreads();
        if (it+1<KT){
            ldg_trans(kb, HD_, l0g, (it+1)*BKQ, tid, pa);
            ldg_trans(hid, DH_, d0g, (it+1)*BKQ, tid, pb);
        }
        compute_3x(sAh,sAl,sBh,sBl,acc,lane,Wm,Wn);
        __syncthreads();
    }
    int g=lane>>2, t4=lane&3;
#pragma unroll
    for (int mt=0;mt<4;mt++){
        int lb = l0g + Wm + mt*16 + g;
        float lr0 = g_lr[(size_t)bn*L_ + lb];
        float lr1 = g_lr[(size_t)bn*L_ + lb + 8];
#pragma unroll
        for (int nt=0;nt<4;nt++){
            int d = d0g + Wn + nt*8 + 2*t4;
#pragma unroll
            for (int rr=0; rr<2; rr++){
                int l = lb + rr*8;
                float lrv = rr ? lr1 : lr0;
                float2 vv = *(const float2*)&g_v[((size_t)b*L_+l)*D_ + d];
                float o0 = lrv*(acc[mt][nt][rr*2+0] - vv.x);
                float o1 = lrv*(acc[mt][nt][rr*2+1] - vv.y);
                *(float2*)&g_A[((size_t)bn*L_+l)*D_ + d] = make_float2(o0,o1);
            }
        }
    }
}

// ---------------- K5: C[l][m] = -(k_l·q_m)*wd_inner[l,m]  (3xTF32, causal tiles) ----------------
__global__ __launch_bounds__(NT) void k_C()
{
    __shared__ __align__(16) float sAh[BKQ*LDT], sAl[BKQ*LDT], sBh[BKQ*LDT], sBl[BKQ*LDT];
    int bn = blockIdx.z;
    int l0g = blockIdx.x*BM, m0g = blockIdx.y*BN;
    if (l0g >= m0g + BN) return;
    const float* kb = g_k + (size_t)bn*L_*HD_;
    const float* qb = g_q + (size_t)bn*L_*HD_;
    int tid = threadIdx.x, lane = tid&31, w = tid>>5;
    int Wm = (w>>2)*64, Wn = (w&3)*32;
    float acc[4][4][4] = {};
    float4 pa[2], pb[2];
    const int KT = HD_/BKQ;
    ldg_trans(kb, HD_, l0g, 0, tid, pa);
    ldg_trans(qb, HD_, m0g, 0, tid, pb);
    for (int it=0; it<KT; ++it){
        sts_trans<true>(pa, 1.f, sAh, sAl, tid);
        sts_trans<true>(pb, 1.f, sBh, sBl, tid);
        __syncthreads();
        if (it+1<KT){
            ldg_trans(kb, HD_, l0g, (it+1)*BKQ, tid, pa);
            ldg_trans(qb, HD_, m0g, (it+1)*BKQ, tid, pb);
        }
        compute_3x(sAh,sAl,sBh,sBl,acc,lane,Wm,Wn);
        __syncthreads();
    }
    float* Cb = g_C + (size_t)bn*L_*L_;
    const float* lwdp = g_lwd + (size_t)bn*L_;
    int g=lane>>2, t4=lane&3;
#pragma unroll
    for (int nt=0;nt<4;nt++){
        int m = m0g + Wn + nt*8 + 2*t4;
        float lw0 = lwdp[m], lw1 = lwdp[m+1];
#pragma unroll
        for (int mt=0;mt<4;mt++){
            int lb = l0g + Wm + mt*16 + g;
#pragma unroll
            for (int rr=0; rr<2; rr++){
                int l = lb + rr*8;
                float o0 = 0.f, o1 = 0.f;
                if (m   >= l) o0 = -acc[mt][nt][rr*2+0] * __expf(lw0 * (float)min(l+1, m));
                if (m+1 >= l) o1 = -acc[mt][nt][rr*2+1] * __expf(lw1 * (float)min(l+1, m+1));
                *(float2*)&Cb[(size_t)l*L_ + m] = make_float2(o0,o1);
            }
        }
    }
}

// ---------------- K6: y = y_cross + sum_l (-C)[l,m]*A[l,d]   (1xTF32, double-buffered) ----------------
__global__ __launch_bounds__(NT) void k_y(const float* __restrict__ hidden,
                                          float* __restrict__ out)
{
    __shared__ __align__(16) float sA[2][BKQ*LDT], sB[2][BKQ*LDT];
    int m0g = blockIdx.x*BM, d0g = blockIdx.y*BN, b = blockIdx.z;
    int tid = threadIdx.x, lane = tid&31, w = tid>>5;
    int Wm = (w>>2)*64, Wn = (w&3)*32;
    float acc[4][4][4] = {};
    float4 pa[2], pb[2];
    for (int n=0; n<NH_; ++n){
        int bn = b*NH_ + n;
        const float* qb  = g_q + (size_t)bn*L_*HD_;
        const float* hid = hidden + (size_t)b*D_*DH_ + n*HD_;
        float msc = g_wdcross[(size_t)bn*L_ + m0g + (tid>>1)];
        // phase 1: cross term, K = 128
        ldg_trans(qb, HD_, m0g, 0, tid, pa);
        ldg_trans(hid, DH_, d0g, 0, tid, pb);
        sts_trans<false>(pa, msc, sA[0], (float*)0, tid);
        sts_trans<false>(pb, 1.f, sB[0], (float*)0, tid);
        __syncthreads();
        for (int it=0; it<8; ++it){
            if (it+1<8){
                ldg_trans(qb, HD_, m0g, (it+1)*BKQ, tid, pa);
                ldg_trans(hid, DH_, d0g, (it+1)*BKQ, tid, pb);
            }
            compute_1x(sA[it&1], sB[it&1], acc, lane, Wm, Wn);
            if (it+1<8){
                sts_trans<false>(pa, msc, sA[(it+1)&1], (float*)0, tid);
                sts_trans<false>(pb, 1.f, sB[(it+1)&1], (float*)0, tid);
            }
            __syncthreads();
        }
        // phase 2: inner term, K = m0g + 128 (causal)
        const float* Cb = g_C + (size_t)bn*L_*L_;
        const float* Ab = g_A + (size_t)bn*L_*D_;
        int KT2 = (m0g + BM)/BKQ;
        ldg_dir(Cb, L_, 0, m0g, tid, pa);
        ldg_dir(Ab, D_, 0, d0g, tid, pb);
        sts_dir<false>(pa, 1.f, 1.f, sA[0], (float*)0, tid);
        sts_dir<false>(pb, 1.f, 1.f, sB[0], (float*)0, tid);
        __syncthreads();
        for (int it=0; it<KT2; ++it){
            if (it+1<KT2){
                ldg_dir(Cb, L_, (it+1)*BKQ, m0g, tid, pa);
                ldg_dir(Ab, D_, (it+1)*BKQ, d0g, tid, pb);
            }
            compute_1x(sA[it&1], sB[it&1], acc, lane, Wm, Wn);
            if (it+1<KT2){
                sts_dir<false>(pa, 1.f, 1.f, sA[(it+1)&1], (float*)0, tid);
                sts_dir<false>(pb, 1.f, 1.f, sB[(it+1)&1], (float*)0, tid);
            }
            __syncthreads();
        }
    }
    int g=lane>>2, t4=lane&3;
#pragma unroll
    for (int mt=0;mt<4;mt++){
        int mb = m0g + Wm + mt*16 + g;
#pragma unroll
        for (int nt=0;nt<4;nt++){
            int d = d0g + Wn + nt*8 + 2*t4;
#pragma unroll
            for (int rr=0; rr<2; rr++){
                int m = mb + rr*8;
                *(float2*)&out[((size_t)b*L_+m)*D_ + d] =
                    make_float2(acc[mt][nt][rr*2+0], acc[mt][nt][rr*2+1]);
            }
        }
    }
}

// ---------------- K7: W_next  (3xTF32) ----------------
__global__ __launch_bounds__(NT) void k_W(const float* __restrict__ hidden,
                                          float* __restrict__ out)
{
    __shared__ __align__(16) float sAh[BKQ*LDT], sAl[BKQ*LDT], sBh[BKQ*LDT], sBl[BKQ*LDT];
    int bn = blockIdx.z, b = bn>>3, n = bn&7;
    int d0g = blockIdx.x*BM;
    const float* Ab = g_A + (size_t)bn*L_*D_;
    const float* kb = g_k + (size_t)bn*L_*HD_;
    const float* wl = g_winl + (size_t)bn*L_;
    int tid = threadIdx.x, lane = tid&31, w = tid>>5;
    int Wm = (w>>2)*64, Wn = (w&3)*32;
    float acc[4][4][4] = {};
    float4 pa[2], pb[2];
    const int KT = L_/BKQ;
    ldg_dir(Ab, D_, 0, d0g, tid, pa);
    ldg_dir(kb, HD_, 0, 0, tid, pb);
    for (int it=0; it<KT; ++it){
        float s0 = wl[it*BKQ + (tid>>5)];
        float s1 = wl[it*BKQ + 8 + (tid>>5)];
        sts_dir<true>(pa, 1.f, 1.f, sAh, sAl, tid);
        sts_dir<true>(pb, s0, s1, sBh, sBl, tid);
        __syncthreads();
        if (it+1<KT){
            ldg_dir(Ab, D_, (it+1)*BKQ, d0g, tid, pa);
            ldg_dir(kb, HD_, (it+1)*BKQ, 0, tid, pb);
        }
        compute_3x(sAh,sAl,sBh,sBl,acc,lane,Wm,Wn);
        __syncthreads();
    }
    const size_t OFFW = (size_t)B_*L_*D_;
    float wdcl = g_wdclast[bn];
    int g=lane>>2, t4=lane&3;
#pragma unroll
    for (int mt=0;mt<4;mt++){
        int db = d0g + Wm + mt*16 + g;
#pragma unroll
        for (int nt=0;nt<4;nt++){
            int h = Wn + nt*8 + 2*t4;
#pragma unroll
            for (int rr=0; rr<2; rr++){
                int d = db + rr*8;
                size_t hidx = (size_t)b*D_*DH_ + (size_t)d*DH_ + n*HD_ + h;
                float2 hv = *(const float2*)&hidden[hidx];
                *(float2*)&out[OFFW + hidx] =
                    make_float2(hv.x*wdcl - acc[mt][nt][rr*2+0],
                                hv.y*wdcl - acc[mt][nt][rr*2+1]);
            }
        }
    }
}

// ---------------- launch ----------------
extern "C" void kernel_launch(void* const* d_in, const int* in_sizes, int n_in,
                              void* d_out, int out_size)
{
    (void)in_sizes; (void)n_in; (void)out_size;
    const float* x           = (const float*)d_in[0];
    const float* hidden      = (const float*)d_in[1];
    const float* log_base_lr = (const float*)d_in[2];
    const float* fc_lr_w     = (const float*)d_in[3];
    const float* fc_lr_b     = (const float*)d_in[4];
    const float* log_base_wd = (const float*)d_in[5];
    const float* fc_wd_w     = (const float*)d_in[6];
    const float* fc_wd_b     = (const float*)d_in[7];
    const float* wq          = (const float*)d_in[8];
    const float* bq          = (const float*)d_in[9];
    const float* wk          = (const float*)d_in[10];
    const float* bk          = (const float*)d_in[11];
    const float* wv          = (const float*)d_in[12];
    const float* bv          = (const float*)d_in[13];
    float* out = (float*)d_out;

    k_proj_qkv<<<dim3(L_/BM, DH_/BN, 3*B_), NT>>>(x, wq, bq, wk, bk, wv, bv);
    k_proj_lrwd<<<(B_*L_*32)/NT, NT>>>(x, fc_lr_w, fc_lr_b, fc_wd_w, fc_wd_b);
    k_scan<<<B_*NH_, NT>>>(log_base_lr, log_base_wd);
    k_A<<<dim3(L_/BM, D_/BN, B_*NH_), NT>>>(hidden);
    k_C<<<dim3(L_/BM, L_/BN, B_*NH_), NT>>>();
    k_y<<<dim3(L_/BM, D_/BN, B_), NT>>>(hidden, out);
    k_W<<<dim3(D_/BM, 1, B_*NH_), NT>>>(hidden, out);
}

// round 10
// speedup vs baseline: 1.0037x; 1.0037x over previous
#include <cuda_runtime.h>
#include <math.h>

#define B_   2
#define L_   2048
#define D_   1024
#define DH_  1024
#define NH_  8
#define HD_  128

#define BM 128
#define BN 128
#define BKQ 16
#define LDT 136
#define NT 256

// ---------------- scratch (device globals; no allocation) ----------------
__device__ float g_q[(size_t)B_*NH_*L_*HD_];      // [b][n][l][h]
__device__ float g_k[(size_t)B_*NH_*L_*HD_];      // [b][n][l][h]
__device__ float g_v[(size_t)B_*L_*D_];           // [b][l][d]
__device__ float g_projlr[(size_t)B_*L_*NH_];
__device__ float g_projwd[(size_t)B_*L_*NH_];
__device__ float g_lr[(size_t)B_*NH_*L_];
__device__ float g_lwd[(size_t)B_*NH_*L_];
__device__ float g_wdcross[(size_t)B_*NH_*L_];
__device__ float g_winl[(size_t)B_*NH_*L_];
__device__ float g_wdclast[B_*NH_];
__device__ float g_A[(size_t)B_*NH_*L_*D_];       // lr[l]*(k·Wp^T - v)   [bn][l][d]
__device__ float g_C[(size_t)B_*NH_*L_*L_];       // NEGATED masked kq    [bn][l][m]

// ---------------- tf32 helpers ----------------
__device__ __forceinline__ unsigned f2tf(float x){
    unsigned r; asm("cvt.rna.tf32.f32 %0, %1;" : "=r"(r) : "f"(x)); return r;
}
__device__ __forceinline__ float tfhi(float x){ return __uint_as_float(f2tf(x)); }

__device__ __forceinline__ void mma8(float (&d)[4], const unsigned (&a)[4], const unsigned (&b)[2]){
    asm volatile("mma.sync.aligned.m16n8k8.row.col.f32.tf32.tf32.f32 "
        "{%0,%1,%2,%3}, {%4,%5,%6,%7}, {%8,%9}, {%0,%1,%2,%3};\n"
        : "+f"(d[0]),"+f"(d[1]),"+f"(d[2]),"+f"(d[3])
        : "r"(a[0]),"r"(a[1]),"r"(a[2]),"r"(a[3]),"r"(b[0]),"r"(b[1]));
}

// ---------------- fragment loads (smem stored [k][m/n], ld=LDT) ----------------
__device__ __forceinline__ void ldfragA(const float* As, int ksb, int Wm, int lane, unsigned (&a)[4][4]){
    int g = lane>>2, t = lane&3;
    const float* p = As + (ksb + t)*LDT + Wm + g;
#pragma unroll
    for (int mt=0; mt<4; mt++){
        a[mt][0] = __float_as_uint(p[mt*16]);
        a[mt][1] = __float_as_uint(p[mt*16+8]);
        a[mt][2] = __float_as_uint(p[4*LDT+mt*16]);
        a[mt][3] = __float_as_uint(p[4*LDT+mt*16+8]);
    }
}
__device__ __forceinline__ void ldfragB(const float* Bs, int ksb, int Wn, int lane, unsigned (&bf)[4][2]){
    int g = lane>>2, t = lane&3;
    const float* p = Bs + (ksb + t)*LDT + Wn + g;
#pragma unroll
    for (int nt=0; nt<4; nt++){
        bf[nt][0] = __float_as_uint(p[nt*8]);
        bf[nt][1] = __float_as_uint(p[4*LDT+nt*8]);
    }
}
__device__ __forceinline__ void mma_tiles(const unsigned (&a)[4][4], const unsigned (&bf)[4][2], float (&acc)[4][4][4]){
#pragma unroll
    for (int mt=0;mt<4;mt++)
#pragma unroll
        for (int nt=0;nt<4;nt++)
            mma8(acc[mt][nt], a[mt], bf[nt]);
}
__device__ __forceinline__ void compute_1x(const float* As, const float* Bs,
                                           float (&acc)[4][4][4], int lane, int Wm, int Wn){
#pragma unroll
    for (int ks=0; ks<2; ks++){
        unsigned a[4][4], bf[4][2];
        ldfragA(As, ks*8, Wm, lane, a);
        ldfragB(Bs, ks*8, Wn, lane, bf);
        mma_tiles(a, bf, acc);
    }
}
__device__ __forceinline__ void compute_3x(const float* Ah, const float* Al,
                                           const float* Bh, const float* Bl,
                                           float (&acc)[4][4][4], int lane, int Wm, int Wn){
#pragma unroll
    for (int ks=0; ks<2; ks++){
        unsigned ah[4][4], al[4][4], bh[4][2], bl[4][2];
        ldfragA(Ah, ks*8, Wm, lane, ah);
        ldfragB(Bh, ks*8, Wn, lane, bh);
        mma_tiles(ah, bh, acc);
        ldfragA(Al, ks*8, Wm, lane, al);
        mma_tiles(al, bh, acc);
        ldfragB(Bl, ks*8, Wn, lane, bl);
        mma_tiles(ah, bl, acc);
    }
}

// ---------------- tile loaders (split ldg / sts for pipelining) ----------------
// transpose: src row-major [R][K], dst[k][r]
__device__ __forceinline__ void ldg_trans(const float* src, int sld, int r0, int k0, int tid, float4 (&o)[2]){
    const float* p = src + (size_t)(r0 + (tid>>1))*sld + k0 + (tid&1)*4;
    o[0] = *(const float4*)(p);
    o[1] = *(const float4*)(p+8);
}
template<bool SPLIT>
__device__ __forceinline__ void sts_trans(const float4 (&o)[2], float s, float* dhi, float* dlo, int tid){
    int r = tid>>1, kk=(tid&1)*4;
#pragma unroll
    for (int p=0;p<2;p++){
        float vv[4]={o[p].x,o[p].y,o[p].z,o[p].w};
#pragma unroll
        for (int i=0;i<4;i++){
            float x = vv[i]*s;
            float hi = tfhi(x);
            dhi[(kk+8*p+i)*LDT + r] = hi;
            if (SPLIT) dlo[(kk+8*p+i)*LDT + r] = tfhi(x-hi);
        }
    }
}
// direct: src row-major [K][N], dst[k][n]
__device__ __forceinline__ void ldg_dir(const float* src, int sld, int k0, int n0, int tid, float4 (&o)[2]){
    const float* p = src + (size_t)(k0 + (tid>>5))*sld + n0 + (tid&31)*4;
    o[0] = *(const float4*)(p);
    o[1] = *(const float4*)(p + (size_t)8*sld);
}
template<bool SPLIT>
__device__ __forceinline__ void sts_dir(const float4 (&o)[2], float s0, float s1, float* dhi, float* dlo, int tid){
    int k = tid>>5, n=(tid&31)*4;
    float sc[2]={s0,s1};
#pragma unroll
    for (int p=0;p<2;p++){
        float vv[4]={o[p].x,o[p].y,o[p].z,o[p].w};
        float h4[4], lo4[4];
#pragma unroll
        for (int i=0;i<4;i++){
            float x=vv[i]*sc[p];
            h4[i]=tfhi(x);
            lo4[i]= SPLIT? tfhi(x-h4[i]) : 0.f;
        }
        *(float4*)(dhi + (k+8*p)*LDT + n) = make_float4(h4[0],h4[1],h4[2],h4[3]);
        if (SPLIT) *(float4*)(dlo + (k+8*p)*LDT + n) = make_float4(lo4[0],lo4[1],lo4[2],lo4[3]);
    }
}

// ---------------- K1: Q/K/V projections (3xTF32) ----------------
__global__ __launch_bounds__(NT) void k_proj_qkv(
    const float* __restrict__ x,
    const float* __restrict__ wq, const float* __restrict__ bq,
    const float* __restrict__ wk, const float* __restrict__ bk,
    const float* __restrict__ wv, const float* __restrict__ bv)
{
    __shared__ __align__(16) float sAh[BKQ*LDT], sAl[BKQ*LDT], sBh[BKQ*LDT], sBl[BKQ*LDT];
    int t = blockIdx.z % 3, b = blockIdx.z / 3;
    const float* W    = (t==0)?wq:((t==1)?wk:wv);
    const float* bias = (t==0)?bq:((t==1)?bk:bv);
    int m0g = blockIdx.x*BM, n0g = blockIdx.y*BN;
    const float* Xb = x + (size_t)b*L_*D_;
    int tid = threadIdx.x, lane = tid&31, w = tid>>5;
    int Wm = (w>>2)*64, Wn = (w&3)*32;
    float acc[4][4][4] = {};
    float4 pa[2], pb[2];
    const int KT = D_/BKQ;
    ldg_trans(Xb, D_, m0g, 0, tid, pa);
    ldg_dir(W, DH_, 0, n0g, tid, pb);
    for (int it=0; it<KT; ++it){
        sts_trans<true>(pa, 1.f, sAh, sAl, tid);
        sts_dir<true>(pb, 1.f, 1.f, sBh, sBl, tid);
        __syncthreads();
        if (it+1<KT){
            ldg_trans(Xb, D_, m0g, (it+1)*BKQ, tid, pa);
            ldg_dir(W, DH_, (it+1)*BKQ, n0g, tid, pb);
        }
        compute_3x(sAh,sAl,sBh,sBl,acc,lane,Wm,Wn);
        __syncthreads();
    }
    int g=lane>>2, t4=lane&3;
#pragma unroll
    for (int mt=0;mt<4;mt++){
        int mb = m0g + Wm + mt*16 + g;
#pragma unroll
        for (int nt=0;nt<4;nt++){
            int jg = n0g + Wn + nt*8 + 2*t4;
            float b0 = bias[jg], b1 = bias[jg+1];
#pragma unroll
            for (int rr=0; rr<2; rr++){
                int m = mb + rr*8;
                float v0 = acc[mt][nt][rr*2+0]+b0, v1 = acc[mt][nt][rr*2+1]+b1;
                if (t==2){
                    *(float2*)&g_v[((size_t)b*L_+m)*D_ + jg] = make_float2(v0,v1);
                } else {
                    int hd = jg>>7, h = jg&127;
                    float* dst = (t==0)? g_q : g_k;
                    *(float2*)&dst[(((size_t)b*NH_+hd)*L_+m)*HD_ + h] = make_float2(v0,v1);
                }
            }
        }
    }
}

// ---------------- K2: lr/wd tiny projections ----------------
__global__ __launch_bounds__(NT) void k_proj_lrwd(
    const float* __restrict__ x,
    const float* __restrict__ fclw, const float* __restrict__ fclb,
    const float* __restrict__ fcww, const float* __restrict__ fcwb)
{
    int gw = (blockIdx.x * blockDim.x + threadIdx.x) >> 5;
    int lane = threadIdx.x & 31;
    if (gw >= B_ * L_) return;
    const float* xr = x + (size_t)gw * D_;
    float acc[16];
#pragma unroll
    for (int j = 0; j < 16; ++j) acc[j] = 0.f;
    for (int k = lane; k < D_; k += 32) {
        float xv = xr[k];
        const float* r1 = fclw + k * NH_;
        const float* r2 = fcww + k * NH_;
#pragma unroll
        for (int j = 0; j < 8; ++j) {
            acc[j]     += xv * r1[j];
            acc[8 + j] += xv * r2[j];
        }
    }
#pragma unroll
    for (int off = 16; off; off >>= 1)
#pragma unroll
        for (int j = 0; j < 16; ++j)
            acc[j] += __shfl_xor_sync(0xffffffffu, acc[j], off);
    if (lane == 0) {
#pragma unroll
        for (int j = 0; j < 8; ++j) {
            g_projlr[(size_t)gw * NH_ + j] = acc[j] + fclb[j];
            g_projwd[(size_t)gw * NH_ + j] = acc[8 + j] + fcwb[j];
        }
    }
}

// ---------------- K3: nonlinearity + parallel scan ----------------
__global__ __launch_bounds__(NT) void k_scan(
    const float* __restrict__ log_base_lr, const float* __restrict__ log_base_wd)
{
    __shared__ float s_lwd[L_];
    __shared__ float sp[NT];
    int bn = blockIdx.x, b = bn >> 3, n = bn & 7;
    int tid = threadIdx.x;
    float blr = expf(log_base_lr[n]);
    float bwd = expf(log_base_wd[n]);
    for (int l = tid; l < L_; l += NT) {
        float plr = g_projlr[((size_t)b*L_+l)*NH_ + n];
        g_lr[(size_t)bn*L_ + l] = blr / (1.f + expf(-plr));
        float pwd = g_projwd[((size_t)b*L_+l)*NH_ + n];
        float lwd = log1pf(-bwd / (1.f + expf(-pwd)));
        s_lwd[l] = lwd;
        g_lwd[(size_t)bn*L_ + l] = lwd;
    }
    __syncthreads();
    // per-thread 8-chunk sums
    const int CH = L_/NT; // 8
    float loc[CH];
    float part = 0.f;
#pragma unroll
    for (int i=0;i<CH;i++){ loc[i] = s_lwd[tid*CH + i]; part += loc[i]; }
    sp[tid] = part;
    __syncthreads();
    for (int off=1; off<NT; off<<=1){
        float v = (tid>=off)? sp[tid-off] : 0.f;
        __syncthreads();
        sp[tid] += v;
        __syncthreads();
    }
    float pre = sp[tid] - part;  // exclusive prefix of this chunk
    float lwdlast = s_lwd[L_-1];
    float run = pre;
#pragma unroll
    for (int i=0;i<CH;i++){
        int l = tid*CH + i;
        run += loc[i];
        g_wdcross[(size_t)bn*L_ + l] = expf(run);
        int mn = min(l+1, L_-1);
        g_winl[(size_t)bn*L_ + l] = expf(lwdlast * (float)mn);
    }
    if (tid == NT-1) g_wdclast[bn] = expf(sp[NT-1]);
}

// ---------------- K4: A = lr*(k·Wp^T - v)   (3xTF32) ----------------
__global__ __launch_bounds__(NT) void k_A(const float* __restrict__ hidden)
{
    __shared__ __align__(16) float sAh[BKQ*LDT], sAl[BKQ*LDT], sBh[BKQ*LDT], sBl[BKQ*LDT];
    int bn = blockIdx.z, b = bn>>3, n = bn&7;
    int l0g = blockIdx.x*BM, d0g = blockIdx.y*BN;
    const float* kb  = g_k + (size_t)bn*L_*HD_;
    const float* hid = hidden + (size_t)b*D_*DH_ + n*HD_;
    int tid = threadIdx.x, lane = tid&31, w = tid>>5;
    int Wm = (w>>2)*64, Wn = (w&3)*32;
    float acc[4][4][4] = {};
    float4 pa[2], pb[2];
    const int KT = HD_/BKQ;
    ldg_trans(kb, HD_, l0g, 0, tid, pa);
    ldg_trans(hid, DH_, d0g, 0, tid, pb);
    for (int it=0; it<KT; ++it){
        sts_trans<true>(pa, 1.f, sAh, sAl, tid);
        sts_trans<true>(pb, 1.f, sBh, sBl, tid);
        __syncthreads();
        if (it+1<KT){
            ldg_trans(kb, HD_, l0g, (it+1)*BKQ, tid, pa);
            ldg_trans(hid, DH_, d0g, (it+1)*BKQ, tid, pb);
        }
        compute_3x(sAh,sAl,sBh,sBl,acc,lane,Wm,Wn);
        __syncthreads();
    }
    int g=lane>>2, t4=lane&3;
#pragma unroll
    for (int mt=0;mt<4;mt++){
        int lb = l0g + Wm + mt*16 + g;
        float lr0 = g_lr[(size_t)bn*L_ + lb];
        float lr1 = g_lr[(size_t)bn*L_ + lb + 8];
#pragma unroll
        for (int nt=0;nt<4;nt++){
            int d = d0g + Wn + nt*8 + 2*t4;
#pragma unroll
            for (int rr=0; rr<2; rr++){
                int l = lb + rr*8;
                float lrv = rr ? lr1 : lr0;
                float2 vv = *(const float2*)&g_v[((size_t)b*L_+l)*D_ + d];
                float o0 = lrv*(acc[mt][nt][rr*2+0] - vv.x);
                float o1 = lrv*(acc[mt][nt][rr*2+1] - vv.y);
                *(float2*)&g_A[((size_t)bn*L_+l)*D_ + d] = make_float2(o0,o1);
            }
        }
    }
}

// ---------------- K5: C[l][m] = -(k_l·q_m)*wd_inner[l,m]  (3xTF32, causal tiles) ----------------
__global__ __launch_bounds__(NT) void k_C()
{
    __shared__ __align__(16) float sAh[BKQ*LDT], sAl[BKQ*LDT], sBh[BKQ*LDT], sBl[BKQ*LDT];
    int bn = blockIdx.z;
    int l0g = blockIdx.x*BM, m0g = blockIdx.y*BN;
    if (l0g >= m0g + BN) return;
    const float* kb = g_k + (size_t)bn*L_*HD_;
    const float* qb = g_q + (size_t)bn*L_*HD_;
    int tid = threadIdx.x, lane = tid&31, w = tid>>5;
    int Wm = (w>>2)*64, Wn = (w&3)*32;
    float acc[4][4][4] = {};
    float4 pa[2], pb[2];
    const int KT = HD_/BKQ;
    ldg_trans(kb, HD_, l0g, 0, tid, pa);
    ldg_trans(qb, HD_, m0g, 0, tid, pb);
    for (int it=0; it<KT; ++it){
        sts_trans<true>(pa, 1.f, sAh, sAl, tid);
        sts_trans<true>(pb, 1.f, sBh, sBl, tid);
        __syncthreads();
        if (it+1<KT){
            ldg_trans(kb, HD_, l0g, (it+1)*BKQ, tid, pa);
            ldg_trans(qb, HD_, m0g, (it+1)*BKQ, tid, pb);
        }
        compute_3x(sAh,sAl,sBh,sBl,acc,lane,Wm,Wn);
        __syncthreads();
    }
    float* Cb = g_C + (size_t)bn*L_*L_;
    const float* lwdp = g_lwd + (size_t)bn*L_;
    int g=lane>>2, t4=lane&3;
#pragma unroll
    for (int nt=0;nt<4;nt++){
        int m = m0g + Wn + nt*8 + 2*t4;
        float lw0 = lwdp[m], lw1 = lwdp[m+1];
#pragma unroll
        for (int mt=0;mt<4;mt++){
            int lb = l0g + Wm + mt*16 + g;
#pragma unroll
            for (int rr=0; rr<2; rr++){
                int l = lb + rr*8;
                float o0 = 0.f, o1 = 0.f;
                if (m   >= l) o0 = -acc[mt][nt][rr*2+0] * __expf(lw0 * (float)min(l+1, m));
                if (m+1 >= l) o1 = -acc[mt][nt][rr*2+1] * __expf(lw1 * (float)min(l+1, m+1));
                *(float2*)&Cb[(size_t)l*L_ + m] = make_float2(o0,o1);
            }
        }
    }
}

// ---------------- K6: y = y_cross + sum_l (-C)[l,m]*A[l,d]   (1xTF32, double-buffered) ----------------
__global__ __launch_bounds__(NT) void k_y(const float* __restrict__ hidden,
                                          float* __restrict__ out)
{
    __shared__ __align__(16) float sA[2][BKQ*LDT], sB[2][BKQ*LDT];
    int m0g = blockIdx.x*BM, d0g = blockIdx.y*BN, b = blockIdx.z;
    int tid = threadIdx.x, lane = tid&31, w = tid>>5;
    int Wm = (w>>2)*64, Wn = (w&3)*32;
    float acc[4][4][4] = {};
    float4 pa[2], pb[2];
    for (int n=0; n<NH_; ++n){
        int bn = b*NH_ + n;
        const float* qb  = g_q + (size_t)bn*L_*HD_;
        const float* hid = hidden + (size_t)b*D_*DH_ + n*HD_;
        float msc = g_wdcross[(size_t)bn*L_ + m0g + (tid>>1)];
        // phase 1: cross term, K = 128
        ldg_trans(qb, HD_, m0g, 0, tid, pa);
        ldg_trans(hid, DH_, d0g, 0, tid, pb);
        sts_trans<false>(pa, msc, sA[0], (float*)0, tid);
        sts_trans<false>(pb, 1.f, sB[0], (float*)0, tid);
        __syncthreads();
        for (int it=0; it<8; ++it){
            if (it+1<8){
                ldg_trans(qb, HD_, m0g, (it+1)*BKQ, tid, pa);
                ldg_trans(hid, DH_, d0g, (it+1)*BKQ, tid, pb);
            }
            compute_1x(sA[it&1], sB[it&1], acc, lane, Wm, Wn);
            if (it+1<8){
                sts_trans<false>(pa, msc, sA[(it+1)&1], (float*)0, tid);
                sts_trans<false>(pb, 1.f, sB[(it+1)&1], (float*)0, tid);
            }
            __syncthreads();
        }
        // phase 2: inner term, K = m0g + 128 (causal)
        const float* Cb = g_C + (size_t)bn*L_*L_;
        const float* Ab = g_A + (size_t)bn*L_*D_;
        int KT2 = (m0g + BM)/BKQ;
        ldg_dir(Cb, L_, 0, m0g, tid, pa);
        ldg_dir(Ab, D_, 0, d0g, tid, pb);
        sts_dir<false>(pa, 1.f, 1.f, sA[0], (float*)0, tid);
        sts_dir<false>(pb, 1.f, 1.f, sB[0], (float*)0, tid);
        __syncthreads();
        for (int it=0; it<KT2; ++it){
            if (it+1<KT2){
                ldg_dir(Cb, L_, (it+1)*BKQ, m0g, tid, pa);
                ldg_dir(Ab, D_, (it+1)*BKQ, d0g, tid, pb);
            }
            compute_1x(sA[it&1], sB[it&1], acc, lane, Wm, Wn);
            if (it+1<KT2){
                sts_dir<false>(pa, 1.f, 1.f, sA[(it+1)&1], (float*)0, tid);
                sts_dir<false>(pb, 1.f, 1.f, sB[(it+1)&1], (float*)0, tid);
            }
            __syncthreads();
        }
    }
    int g=lane>>2, t4=lane&3;
#pragma unroll
    for (int mt=0;mt<4;mt++){
        int mb = m0g + Wm + mt*16 + g;
#pragma unroll
        for (int nt=0;nt<4;nt++){
            int d = d0g + Wn + nt*8 + 2*t4;
#pragma unroll
            for (int rr=0; rr<2; rr++){
                int m = mb + rr*8;
                *(float2*)&out[((size_t)b*L_+m)*D_ + d] =
                    make_float2(acc[mt][nt][rr*2+0], acc[mt][nt][rr*2+1]);
            }
        }
    }
}

// ---------------- K7: W_next  (3xTF32) ----------------
__global__ __launch_bounds__(NT) void k_W(const float* __restrict__ hidden,
                                          float* __restrict__ out)
{
    __shared__ __align__(16) float sAh[BKQ*LDT], sAl[BKQ*LDT], sBh[BKQ*LDT], sBl[BKQ*LDT];
    int bn = blockIdx.z, b = bn>>3, n = bn&7;
    int d0g = blockIdx.x*BM;
    const float* Ab = g_A + (size_t)bn*L_*D_;
    const float* kb = g_k + (size_t)bn*L_*HD_;
    const float* wl = g_winl + (size_t)bn*L_;
    int tid = threadIdx.x, lane = tid&31, w = tid>>5;
    int Wm = (w>>2)*64, Wn = (w&3)*32;
    float acc[4][4][4] = {};
    float4 pa[2], pb[2];
    const int KT = L_/BKQ;
    ldg_dir(Ab, D_, 0, d0g, tid, pa);
    ldg_dir(kb, HD_, 0, 0, tid, pb);
    for (int it=0; it<KT; ++it){
        float s0 = wl[it*BKQ + (tid>>5)];
        float s1 = wl[it*BKQ + 8 + (tid>>5)];
        sts_dir<true>(pa, 1.f, 1.f, sAh, sAl, tid);
        sts_dir<true>(pb, s0, s1, sBh, sBl, tid);
        __syncthreads();
        if (it+1<KT){
            ldg_dir(Ab, D_, (it+1)*BKQ, d0g, tid, pa);
            ldg_dir(kb, HD_, (it+1)*BKQ, 0, tid, pb);
        }
        compute_3x(sAh,sAl,sBh,sBl,acc,lane,Wm,Wn);
        __syncthreads();
    }
    const size_t OFFW = (size_t)B_*L_*D_;
    float wdcl = g_wdclast[bn];
    int g=lane>>2, t4=lane&3;
#pragma unroll
    for (int mt=0;mt<4;mt++){
        int db = d0g + Wm + mt*16 + g;
#pragma unroll
        for (int nt=0;nt<4;nt++){
            int h = Wn + nt*8 + 2*t4;
#pragma unroll
            for (int rr=0; rr<2; rr++){
                int d = db + rr*8;
                size_t hidx = (size_t)b*D_*DH_ + (size_t)d*DH_ + n*HD_ + h;
                float2 hv = *(const float2*)&hidden[hidx];
                *(float2*)&out[OFFW + hidx] =
                    make_float2(hv.x*wdcl - acc[mt][nt][rr*2+0],
                                hv.y*wdcl - acc[mt][nt][rr*2+1]);
            }
        }
    }
}

// ---------------- launch ----------------
extern "C" void kernel_launch(void* const* d_in, const int* in_sizes, int n_in,
                              void* d_out, int out_size)
{
    (void)in_sizes; (void)n_in; (void)out_size;
    const float* x           = (const float*)d_in[0];
    const float* hidden      = (const float*)d_in[1];
    const float* log_base_lr = (const float*)d_in[2];
    const float* fc_lr_w     = (const float*)d_in[3];
    const float* fc_lr_b     = (const float*)d_in[4];
    const float* log_base_wd = (const float*)d_in[5];
    const float* fc_wd_w     = (const float*)d_in[6];
    const float* fc_wd_b     = (const float*)d_in[7];
    const float* wq          = (const float*)d_in[8];
    const float* bq          = (const float*)d_in[9];
    const float* wk          = (const float*)d_in[10];
    const float* bk          = (const float*)d_in[11];
    const float* wv          = (const float*)d_in[12];
    const float* bv          = (const float*)d_in[13];
    float* out = (float*)d_out;

    k_proj_qkv<<<dim3(L_/BM, DH_/BN, 3*B_), NT>>>(x, wq, bq, wk, bk, wv, bv);
    k_proj_lrwd<<<(B_*L_*32)/NT, NT>>>(x, fc_lr_w, fc_lr_b, fc_wd_w, fc_wd_b);
    k_scan<<<B_*NH_, NT>>>(log_base_lr, log_base_wd);
    k_A<<<dim3(L_/BM, D_/BN, B_*NH_), NT>>>(hidden);
    k_C<<<dim3(L_/BM, L_/BN, B_*NH_), NT>>>();
    k_y<<<dim3(L_/BM, D_/BN, B_), NT>>>(hidden, out);
    k_W<<<dim3(D_/BM, 1, B_*NH_), NT>>>(hidden, out);
}